// round 13
// baseline (speedup 1.0000x reference)
#include <cuda_runtime.h>
#include <cuda_bf16.h>
#include <mma.h>
#include <math.h>
#include <stdint.h>

using namespace nvcuda;

// ---------------- problem constants ----------------
#define T_DIM 256
#define B_DIM 256
#define D_DIM 128
#define H_DIM 512
#define G3H   1536            // 3*H
#define TM1   255             // T-1
#define K10D  1280            // 10*D
#define PRE_ROWS (B_DIM*TM1)  // 65280
#define PRED_ELEMS (PRE_ROWS*D_DIM)  // 8355840
#define KXP   192             // padded K for x / w_ih (129 -> 192)
#define BH    (B_DIM*H_DIM)   // 131072

// WMMA GEMM geometry
#define BK     32
#define LDSO   48             // operand smem pitch (bf16 elements, 96B)
#define EPAD   132            // epilogue smem pitch (floats)
#define GEMM_SMEM (128*EPAD*4)   // 67584 B

// persistent GRU geometry (WMMA version)
#define NCTA   128            // 32 k-chunks x 4 batch-groups
#define GTPB   256            // 8 warps; warps 0-5 do MMA
#define WPITCH 520            // w smem pitch (bf16)
#define WELEMS (48*WPITCH)    // 24960 per array
#define BPITCH 72             // h smem pitch (bf16)
#define STG_EL (2*64*BPITCH)  // 9216 elems per stage (hi+lo)
#define ESM_OFF (2*WELEMS*2 + 2*STG_EL*2)   // 136704 bytes
#define GRU_SMEM (ESM_OFF + 48*BPITCH*4)    // 150528 bytes

// ---------------- scratch (static device arrays) ----------------
__device__ float g_xwT[(size_t)T_DIM * G3H * B_DIM];      // [t][col][b] fp32
__device__ float g_td[PRE_ROWS];
__device__ unsigned g_bar[260];

// h state: bf16 hi/lo pairs, [buf][b][k] layout
__device__ __nv_bfloat16 g_hThi[2 * BH];
__device__ __nv_bfloat16 g_hTlo[2 * BH];

// bf16 split operands
__device__ __nv_bfloat16 g_Axhi[(size_t)T_DIM * B_DIM * KXP];
__device__ __nv_bfloat16 g_Axlo[(size_t)T_DIM * B_DIM * KXP];
__device__ __nv_bfloat16 g_Bwihhi[(size_t)G3H * KXP];
__device__ __nv_bfloat16 g_Bwihlo[(size_t)G3H * KXP];
__device__ __nv_bfloat16 g_Ahidhi[(size_t)PRE_ROWS * H_DIM];
__device__ __nv_bfloat16 g_Ahidlo[(size_t)PRE_ROWS * H_DIM];
__device__ __nv_bfloat16 g_Bw1hi[(size_t)K10D * H_DIM];
__device__ __nv_bfloat16 g_Bw1lo[(size_t)K10D * H_DIM];
__device__ __nv_bfloat16 g_Bw2hi[(size_t)D_DIM * K10D];
__device__ __nv_bfloat16 g_Bw2lo[(size_t)D_DIM * K10D];
__device__ __nv_bfloat16 g_Phi[(size_t)PRE_ROWS * K10D];
__device__ __nv_bfloat16 g_Plo[(size_t)PRE_ROWS * K10D];

// ---------------- helpers ----------------
__device__ __forceinline__ float fsigmoid(float x) {
    return __fdividef(1.f, 1.f + __expf(-x));
}
__device__ __forceinline__ float ftanh(float x) {
    return 1.f - __fdividef(2.f, __expf(2.f * x) + 1.f);
}

// =======================================================================
// WMMA split-bf16 GEMM: C[M,N] = A[M,K] * B[N,K]^T  (fp32 accumulate)
// acc += Ahi*Bhi + Alo*Bhi + Ahi*Blo
// CTA tile 128x128, 8 warps (4M x 2N), warp tile 32x64, BK=32.
// MODE 0: xw    -> C[t][col][b] transposed store, + bias
// MODE 1: pre   -> sigmoid(c + td[row]*w1[col*513+512] + bias) -> Phi/Plo
// MODE 2: preds -> c = (t < len[b]-1) ? c+bias : 0  -> C row-major
// =======================================================================
template <int MODE>
__global__ __launch_bounds__(256)
void wgemm(const __nv_bfloat16* __restrict__ Ahi, const __nv_bfloat16* __restrict__ Alo,
           const __nv_bfloat16* __restrict__ Bhi, const __nv_bfloat16* __restrict__ Blo,
           float* __restrict__ C, int K, int lda, int ldb,
           const float* __restrict__ bias, const float* __restrict__ tdv,
           const float* __restrict__ w1f, const int* __restrict__ lengths,
           __nv_bfloat16* __restrict__ Phi, __nv_bfloat16* __restrict__ Plo)
{
    extern __shared__ __align__(16) char smem[];
    __nv_bfloat16* sAhi = (__nv_bfloat16*)smem;            // [128][48]
    __nv_bfloat16* sAlo = sAhi + 128 * LDSO;
    __nv_bfloat16* sBhi = sAlo + 128 * LDSO;
    __nv_bfloat16* sBlo = sBhi + 128 * LDSO;
    float* esm = (float*)smem;                             // [128][132] epilogue

    const int tid = threadIdx.x;
    const int wid = tid >> 5;
    const int lane = tid & 31;
    const int row0 = blockIdx.y * 128;
    const int col0 = blockIdx.x * 128;
    const int wm = (wid & 3) * 32;
    const int wn = (wid >> 2) * 64;

    wmma::fragment<wmma::accumulator, 16, 16, 16, float> acc[2][4];
#pragma unroll
    for (int i = 0; i < 2; i++)
#pragma unroll
        for (int j = 0; j < 4; j++) wmma::fill_fragment(acc[i][j], 0.f);

    // 256 threads cover 128 rows x 32 k in two row halves per operand
    const int lr = tid >> 2, lq = tid & 3;
    const __nv_bfloat16* gAhi0 = Ahi + (size_t)(row0 + lr) * lda + lq * 8;
    const __nv_bfloat16* gAhi1 = gAhi0 + (size_t)64 * lda;
    const __nv_bfloat16* gAlo0 = Alo + (size_t)(row0 + lr) * lda + lq * 8;
    const __nv_bfloat16* gAlo1 = gAlo0 + (size_t)64 * lda;
    const __nv_bfloat16* gBhi0 = Bhi + (size_t)(col0 + lr) * ldb + lq * 8;
    const __nv_bfloat16* gBhi1 = gBhi0 + (size_t)64 * ldb;
    const __nv_bfloat16* gBlo0 = Blo + (size_t)(col0 + lr) * ldb + lq * 8;
    const __nv_bfloat16* gBlo1 = gBlo0 + (size_t)64 * ldb;
    const int soff0 = lr * LDSO + lq * 8;
    const int soff1 = (lr + 64) * LDSO + lq * 8;

#pragma unroll 1
    for (int kc = 0; kc < K; kc += BK) {
        __syncthreads();
        *(uint4*)(sAhi + soff0) = *(const uint4*)(gAhi0 + kc);
        *(uint4*)(sAhi + soff1) = *(const uint4*)(gAhi1 + kc);
        *(uint4*)(sAlo + soff0) = *(const uint4*)(gAlo0 + kc);
        *(uint4*)(sAlo + soff1) = *(const uint4*)(gAlo1 + kc);
        *(uint4*)(sBhi + soff0) = *(const uint4*)(gBhi0 + kc);
        *(uint4*)(sBhi + soff1) = *(const uint4*)(gBhi1 + kc);
        *(uint4*)(sBlo + soff0) = *(const uint4*)(gBlo0 + kc);
        *(uint4*)(sBlo + soff1) = *(const uint4*)(gBlo1 + kc);
        __syncthreads();

#pragma unroll
        for (int ks = 0; ks < BK; ks += 16) {
            wmma::fragment<wmma::matrix_a, 16, 16, 16, __nv_bfloat16, wmma::row_major> ahi[2], alo[2];
#pragma unroll
            for (int i = 0; i < 2; i++) {
                wmma::load_matrix_sync(ahi[i], sAhi + (wm + 16 * i) * LDSO + ks, LDSO);
                wmma::load_matrix_sync(alo[i], sAlo + (wm + 16 * i) * LDSO + ks, LDSO);
            }
#pragma unroll
            for (int j = 0; j < 4; j++) {
                wmma::fragment<wmma::matrix_b, 16, 16, 16, __nv_bfloat16, wmma::col_major> bhi, blo;
                wmma::load_matrix_sync(bhi, sBhi + (wn + 16 * j) * LDSO + ks, LDSO);
                wmma::load_matrix_sync(blo, sBlo + (wn + 16 * j) * LDSO + ks, LDSO);
#pragma unroll
                for (int i = 0; i < 2; i++) {
                    wmma::mma_sync(acc[i][j], ahi[i], bhi, acc[i][j]);
                    wmma::mma_sync(acc[i][j], alo[i], bhi, acc[i][j]);
                    wmma::mma_sync(acc[i][j], ahi[i], blo, acc[i][j]);
                }
            }
        }
    }

    __syncthreads();
#pragma unroll
    for (int i = 0; i < 2; i++)
#pragma unroll
        for (int j = 0; j < 4; j++)
            wmma::store_matrix_sync(esm + (wm + 16 * i) * EPAD + wn + 16 * j,
                                    acc[i][j], EPAD, wmma::mem_row_major);
    __syncthreads();

    if (MODE == 0) {
        const int tt = row0 >> 8;
        const int bb0 = row0 & 255;
#pragma unroll 1
        for (int cc = wid; cc < 128; cc += 8) {
            const int col = col0 + cc;
            const float bz = bias[col];
            float* dst = C + ((size_t)tt * G3H + col) * B_DIM + bb0;
#pragma unroll
            for (int rr = lane; rr < 128; rr += 32)
                dst[rr] = esm[rr * EPAD + cc] + bz;
        }
    } else if (MODE == 1) {
        const int r = tid >> 1, h = tid & 1;
        const int grow = row0 + r;
        const float tdval = tdv[grow];
        const float* esrow = esm + r * EPAD + h * 64;
        const size_t obase = (size_t)grow * K10D + col0 + h * 64;
#pragma unroll
        for (int g = 0; g < 2; g++) {
            uint32_t hp[16], lp[16];
#pragma unroll
            for (int q = 0; q < 16; q++) {
                const int c0 = g * 32 + q * 2;
                const int col = col0 + h * 64 + c0;
                float v0 = esrow[c0]     + bias[col]
                         + tdval * w1f[(size_t)col * 513 + 512];
                float v1 = esrow[c0 + 1] + bias[col + 1]
                         + tdval * w1f[(size_t)(col + 1) * 513 + 512];
                float s0 = fsigmoid(v0);
                float s1 = fsigmoid(v1);
                __nv_bfloat16 h0 = __float2bfloat16(s0);
                __nv_bfloat16 h1 = __float2bfloat16(s1);
                __nv_bfloat16 l0 = __float2bfloat16(s0 - __bfloat162float(h0));
                __nv_bfloat16 l1 = __float2bfloat16(s1 - __bfloat162float(h1));
                __nv_bfloat162 hh = __halves2bfloat162(h0, h1);
                __nv_bfloat162 ll = __halves2bfloat162(l0, l1);
                hp[q] = *(uint32_t*)&hh;
                lp[q] = *(uint32_t*)&ll;
            }
#pragma unroll
            for (int q = 0; q < 4; q++) {
                *(uint4*)(Phi + obase + g * 32 + q * 8) = ((uint4*)hp)[q];
                *(uint4*)(Plo + obase + g * 32 + q * 8) = ((uint4*)lp)[q];
            }
        }
    } else { // MODE 2
        const int r = tid >> 1, h = tid & 1;
        const int grow = row0 + r;
        const int b_ = grow / 255;
        const int t_ = grow - b_ * 255;
        const bool valid = t_ < lengths[b_] - 1;
        const float* esrow = esm + r * EPAD + h * 64;
        float* dst = C + (size_t)grow * D_DIM + col0 + h * 64;
#pragma unroll
        for (int q = 0; q < 16; q++) {
            const int c0 = q * 4;
            const int col = col0 + h * 64 + c0;
            float4 v;
            v.x = valid ? (esrow[c0]     + bias[col])     : 0.f;
            v.y = valid ? (esrow[c0 + 1] + bias[col + 1]) : 0.f;
            v.z = valid ? (esrow[c0 + 2] + bias[col + 2]) : 0.f;
            v.w = valid ? (esrow[c0 + 3] + bias[col + 3]) : 0.f;
            *(float4*)(dst + c0) = v;
        }
    }
}

// =======================================================================
// conversions: fp32 -> bf16 hi/lo with zero-padding
// =======================================================================
__global__ void conv_pad(const float* __restrict__ src,
                         __nv_bfloat16* __restrict__ hi,
                         __nv_bfloat16* __restrict__ lo,
                         int rows, int sld, int dld, int valid)
{
    int i = blockIdx.x * 256 + threadIdx.x;
    if (i >= rows * dld) return;
    int r = i / dld, c = i - r * dld;
    float v = (c < valid) ? src[(size_t)r * sld + c] : 0.f;
    __nv_bfloat16 h = __float2bfloat16(v);
    hi[i] = h;
    lo[i] = __float2bfloat16(v - __bfloat162float(h));
}

// =======================================================================
// Persistent GRU on tensor cores. 128 CTAs (1/SM), 256 steps, 8 warps.
// CTA (jc,bg): units [jc*16,jc*16+16) x 3 gates, batches [bg*64,bg*64+64).
// w_hh slice in SMEM as bf16 hi/lo [48][520] (rows = g*16+u).
// h in global bf16 hi/lo pairs, [buf][b][k] layout.
// Per step: 8 k-chunks of 64, warps 0..5 do WMMA (3-product split-bf16),
// acc staged to SMEM, epilogue computes gates + writes h and Ahid.
// =======================================================================
__global__ __launch_bounds__(GTPB, 1)
void gru_wmma(const float* __restrict__ h0,
              const float* __restrict__ xwT,
              const float* __restrict__ w_hh,
              const float* __restrict__ b_hh,
              const int*   __restrict__ lengths,
              __nv_bfloat16* __restrict__ hThi,
              __nv_bfloat16* __restrict__ hTlo,
              __nv_bfloat16* __restrict__ Ahidhi,
              __nv_bfloat16* __restrict__ Ahidlo,
              unsigned* __restrict__ bar)
{
    extern __shared__ __align__(16) char sm[];
    __nv_bfloat16* sWhi = (__nv_bfloat16*)sm;             // [48][520]
    __nv_bfloat16* sWlo = sWhi + WELEMS;
    __nv_bfloat16* sB   = sWlo + WELEMS;                  // [2 stg][2][64][72]
    float* esm = (float*)(sm + ESM_OFF);                  // [48][72]

    const int tid = threadIdx.x;
    const int wid = tid >> 5;
    const int jc  = blockIdx.x & 31;
    const int bgi = blockIdx.x >> 5;
    const int ubase = jc * 16;
    const int bbase = bgi * 64;

    // ---- one-time: w_hh slice -> SMEM bf16 hi/lo, rows = g*16+u
    for (int i = tid; i < 48 * 512; i += GTPB) {
        int row = i >> 9, k = i & 511;
        int g = row >> 4, u = row & 15;
        float v = w_hh[(size_t)(g * H_DIM + ubase + u) * H_DIM + k];
        __nv_bfloat16 h = __float2bfloat16(v);
        sWhi[row * WPITCH + k] = h;
        sWlo[row * WPITCH + k] = __float2bfloat16(v - __bfloat162float(h));
    }
    // ---- one-time: own tile of h0 -> hT buf0 ([b][k] bf16 pair)
    for (int i = tid; i < 1024; i += GTPB) {
        int b = i >> 4, u = i & 15;
        float v = h0[(size_t)(bbase + b) * H_DIM + ubase + u];
        __nv_bfloat16 h = __float2bfloat16(v);
        size_t a = (size_t)(bbase + b) * H_DIM + ubase + u;
        hThi[a] = h;
        hTlo[a] = __float2bfloat16(v - __bfloat162float(h));
    }
    __syncthreads();
    if (tid == 0) {
        __threadfence();
        atomicAdd(&bar[0], 1u);
        volatile unsigned* f = &bar[0];
        while (*f < (unsigned)NCTA) __nanosleep(64);
    }
    __syncthreads();

    const int g_w = wid >> 1;      // compute-warp gate (wid<6)
    const int bh_w = wid & 1;      // compute-warp batch half

    for (int t = 0; t < T_DIM; t++) {
        const __nv_bfloat16* hHi = hThi + (size_t)(t & 1) * BH;
        const __nv_bfloat16* hLo = hTlo + (size_t)(t & 1) * BH;
        __nv_bfloat16* nHi = hThi + (size_t)((t + 1) & 1) * BH;
        __nv_bfloat16* nLo = hTlo + (size_t)((t + 1) & 1) * BH;

        wmma::fragment<wmma::accumulator, 16, 16, 16, float> acc[2];
        wmma::fill_fragment(acc[0], 0.f);
        wmma::fill_fragment(acc[1], 0.f);

        // prefetch chunk 0: 1024 uint4 (hi:512, lo:512) / 256 threads = 4
        uint4 pf[4];
#pragma unroll
        for (int s = 0; s < 4; s++) {
            int j = tid + s * GTPB;
            int arr = j >> 9, jj = j & 511;
            int b = jj >> 3, q = jj & 7;
            const __nv_bfloat16* src = arr ? hLo : hHi;
            pf[s] = __ldcg((const uint4*)(src + (size_t)(bbase + b) * H_DIM + q * 8));
        }

#pragma unroll 1
        for (int c = 0; c < 8; c++) {
            // store prefetched chunk into stage c&1
#pragma unroll
            for (int s = 0; s < 4; s++) {
                int j = tid + s * GTPB;
                int arr = j >> 9, jj = j & 511;
                int b = jj >> 3, q = jj & 7;
                *(uint4*)(sB + (c & 1) * STG_EL + arr * (64 * BPITCH)
                          + b * BPITCH + q * 8) = pf[s];
            }
            if (c < 7) {
#pragma unroll
                for (int s = 0; s < 4; s++) {
                    int j = tid + s * GTPB;
                    int arr = j >> 9, jj = j & 511;
                    int b = jj >> 3, q = jj & 7;
                    const __nv_bfloat16* src = arr ? hLo : hHi;
                    pf[s] = __ldcg((const uint4*)(src + (size_t)(bbase + b) * H_DIM
                                                  + (c + 1) * 64 + q * 8));
                }
            }
            __syncthreads();

            if (wid < 6) {
                const __nv_bfloat16* sHhi = sB + (c & 1) * STG_EL;
                const __nv_bfloat16* sHlo = sHhi + 64 * BPITCH;
#pragma unroll
                for (int ks = 0; ks < 64; ks += 16) {
                    wmma::fragment<wmma::matrix_a, 16, 16, 16, __nv_bfloat16, wmma::row_major> ahi, alo;
                    wmma::load_matrix_sync(ahi, sWhi + (g_w * 16) * WPITCH + c * 64 + ks, WPITCH);
                    wmma::load_matrix_sync(alo, sWlo + (g_w * 16) * WPITCH + c * 64 + ks, WPITCH);
#pragma unroll
                    for (int j = 0; j < 2; j++) {
                        wmma::fragment<wmma::matrix_b, 16, 16, 16, __nv_bfloat16, wmma::col_major> bhi, blo;
                        const int ncol = bh_w * 32 + j * 16;
                        wmma::load_matrix_sync(bhi, sHhi + ncol * BPITCH + ks, BPITCH);
                        wmma::load_matrix_sync(blo, sHlo + ncol * BPITCH + ks, BPITCH);
                        wmma::mma_sync(acc[j], ahi, bhi, acc[j]);
                        wmma::mma_sync(acc[j], alo, bhi, acc[j]);
                        wmma::mma_sync(acc[j], ahi, blo, acc[j]);
                    }
                }
            }
        }

        // stage gate pre-activations to esm [48][72]
        if (wid < 6) {
#pragma unroll
            for (int j = 0; j < 2; j++)
                wmma::store_matrix_sync(esm + (g_w * 16) * BPITCH + bh_w * 32 + j * 16,
                                        acc[j], BPITCH, wmma::mem_row_major);
        }
        __syncthreads();

        // ---- epilogue: 1024 outputs (16 units x 64 batches), 4 per thread
#pragma unroll
        for (int s = 0; s < 4; s++) {
            int i = tid + s * GTPB;
            int u = i >> 6, b = i & 63;
            int ug = ubase + u, bg = bbase + b;
            float ar = esm[(0 * 16 + u) * BPITCH + b];
            float az = esm[(1 * 16 + u) * BPITCH + b];
            float an = esm[(2 * 16 + u) * BPITCH + b];
            size_t xb = ((size_t)t * G3H + ug) * B_DIM + bg;
            float xr = __ldg(xwT + xb);
            float xz = __ldg(xwT + xb + (size_t)H_DIM * B_DIM);
            float xn = __ldg(xwT + xb + (size_t)2 * H_DIM * B_DIM);
            size_t ha = (size_t)bg * H_DIM + ug;
            float hold = __bfloat162float(hHi[ha]) + __bfloat162float(hLo[ha]);
            float r = fsigmoid(xr + ar + b_hh[ug]);
            float z = fsigmoid(xz + az + b_hh[H_DIM + ug]);
            float n = ftanh(xn + r * (an + b_hh[2 * H_DIM + ug]));
            float hnew = (1.f - z) * n + z * hold;
            bool valid = t < lengths[bg];
            float hout = valid ? hnew : hold;
            __nv_bfloat16 hh = __float2bfloat16(hout);
            nHi[ha] = hh;
            nLo[ha] = __float2bfloat16(hout - __bfloat162float(hh));
            if (t < TM1) {
                float hv = valid ? hnew : 0.f;
                __nv_bfloat16 ah = __float2bfloat16(hv);
                size_t aa = ((size_t)bg * TM1 + t) * H_DIM + ug;
                Ahidhi[aa] = ah;
                Ahidlo[aa] = __float2bfloat16(hv - __bfloat162float(ah));
            }
        }

        __syncthreads();
        if (tid == 0) {
            __threadfence();
            atomicAdd(&bar[t + 1], 1u);
            volatile unsigned* f = &bar[t + 1];
            while (*f < (unsigned)NCTA) __nanosleep(64);
        }
        __syncthreads();
    }
}

// =======================================================================
__global__ void td_kernel(const float* __restrict__ x, float* __restrict__ td)
{
    int i = blockIdx.x * 256 + threadIdx.x;
    if (i < PRE_ROWS) {
        int b = i / 255;
        int t = i - b * 255;
        td[i] = x[(size_t)((t + 1) * B_DIM + b) * (D_DIM + 1)]
              - x[(size_t)(t * B_DIM + b) * (D_DIM + 1)];
    }
}

// =======================================================================
// dist_params + lengths; final h is hT buf0, [b][k] bf16 pair layout
// =======================================================================
__global__ void tail_kernel(const __nv_bfloat16* __restrict__ hHi,
                            const __nv_bfloat16* __restrict__ hLo,
                            const float* __restrict__ wp,
                            const float* __restrict__ bp,
                            const int* __restrict__ lengths,
                            float* __restrict__ out)
{
    int b = blockIdx.x;
    int w = threadIdx.x >> 5;
    int lane = threadIdx.x & 31;
    float s = 0.f;
    for (int k = lane; k < H_DIM; k += 32) {
        float hv = __bfloat162float(hHi[(size_t)b * H_DIM + k])
                 + __bfloat162float(hLo[(size_t)b * H_DIM + k]);
        s += hv * wp[(size_t)w * H_DIM + k];
    }
#pragma unroll
    for (int o = 16; o; o >>= 1) s += __shfl_xor_sync(0xffffffffu, s, o);
    if (lane == 0)
        out[PRED_ELEMS + b * 3 + w] = expf(-(s + bp[w]));
    if (threadIdx.x == 0)
        out[PRED_ELEMS + B_DIM * 3 + b] = (float)lengths[b];
}

// =======================================================================
extern "C" void kernel_launch(void* const* d_in, const int* in_sizes, int n_in,
                              void* d_out, int out_size)
{
    const float* x    = (const float*)d_in[0];
    const float* h0   = (const float*)d_in[1];
    const int*   lens = (const int*)  d_in[2];
    const float* w_ih = (const float*)d_in[3];
    const float* w_hh = (const float*)d_in[4];
    const float* b_ih = (const float*)d_in[5];
    const float* b_hh = (const float*)d_in[6];
    const float* w1   = (const float*)d_in[7];
    const float* b1   = (const float*)d_in[8];
    const float* w2   = (const float*)d_in[9];
    const float* b2   = (const float*)d_in[10];
    const float* wp   = (const float*)d_in[11];
    const float* bp   = (const float*)d_in[12];
    float* out = (float*)d_out;

    float *xwT, *td;
    unsigned* bar;
    __nv_bfloat16 *hThi, *hTlo;
    __nv_bfloat16 *Axhi, *Axlo, *Bwihhi, *Bwihlo, *Ahidhi, *Ahidlo;
    __nv_bfloat16 *Bw1hi, *Bw1lo, *Bw2hi, *Bw2lo, *Phi, *Plo;
    cudaGetSymbolAddress((void**)&xwT,    g_xwT);
    cudaGetSymbolAddress((void**)&td,     g_td);
    cudaGetSymbolAddress((void**)&bar,    g_bar);
    cudaGetSymbolAddress((void**)&hThi,   g_hThi);
    cudaGetSymbolAddress((void**)&hTlo,   g_hTlo);
    cudaGetSymbolAddress((void**)&Axhi,   g_Axhi);
    cudaGetSymbolAddress((void**)&Axlo,   g_Axlo);
    cudaGetSymbolAddress((void**)&Bwihhi, g_Bwihhi);
    cudaGetSymbolAddress((void**)&Bwihlo, g_Bwihlo);
    cudaGetSymbolAddress((void**)&Ahidhi, g_Ahidhi);
    cudaGetSymbolAddress((void**)&Ahidlo, g_Ahidlo);
    cudaGetSymbolAddress((void**)&Bw1hi,  g_Bw1hi);
    cudaGetSymbolAddress((void**)&Bw1lo,  g_Bw1lo);
    cudaGetSymbolAddress((void**)&Bw2hi,  g_Bw2hi);
    cudaGetSymbolAddress((void**)&Bw2lo,  g_Bw2lo);
    cudaGetSymbolAddress((void**)&Phi,    g_Phi);
    cudaGetSymbolAddress((void**)&Plo,    g_Plo);

    cudaFuncSetAttribute(gru_wmma,
                         cudaFuncAttributeMaxDynamicSharedMemorySize, GRU_SMEM);
    cudaFuncSetAttribute(wgemm<0>,
                         cudaFuncAttributeMaxDynamicSharedMemorySize, GEMM_SMEM);
    cudaFuncSetAttribute(wgemm<1>,
                         cudaFuncAttributeMaxDynamicSharedMemorySize, GEMM_SMEM);
    cudaFuncSetAttribute(wgemm<2>,
                         cudaFuncAttributeMaxDynamicSharedMemorySize, GEMM_SMEM);

    cudaMemsetAsync(bar, 0, 260 * sizeof(unsigned));

    td_kernel<<<255, 256>>>(x, td);

    // conversions for gemm0 operands
    conv_pad<<<(T_DIM * B_DIM * KXP + 255) / 256, 256>>>(
        x, Axhi, Axlo, T_DIM * B_DIM, D_DIM + 1, KXP, D_DIM + 1);
    conv_pad<<<(G3H * KXP + 255) / 256, 256>>>(
        w_ih, Bwihhi, Bwihlo, G3H, D_DIM + 1, KXP, D_DIM + 1);
    // weights for later gemms
    conv_pad<<<(K10D * H_DIM + 255) / 256, 256>>>(
        w1, Bw1hi, Bw1lo, K10D, H_DIM + 1, H_DIM, H_DIM);
    conv_pad<<<(D_DIM * K10D + 255) / 256, 256>>>(
        w2, Bw2hi, Bw2lo, D_DIM, K10D, K10D, K10D);

    // xwT = (x @ w_ih^T + b_ih) transposed -> [t][col][b]
    wgemm<0><<<dim3(G3H / 128, (T_DIM * B_DIM) / 128), 256, GEMM_SMEM>>>(
        Axhi, Axlo, Bwihhi, Bwihlo, xwT, KXP, KXP, KXP,
        b_ih, nullptr, nullptr, nullptr, nullptr, nullptr);

    // persistent tensor-core GRU (all 256 steps); writes Ahid directly
    gru_wmma<<<NCTA, GTPB, GRU_SMEM>>>(h0, xwT, w_hh, b_hh, lens,
                                       hThi, hTlo, Ahidhi, Ahidlo, bar);

    // pre = sigmoid(hwt[:, :-1] @ w1^T + b1) -> Phi/Plo (bf16 split)
    wgemm<1><<<dim3(K10D / 128, PRE_ROWS / 128), 256, GEMM_SMEM>>>(
        Ahidhi, Ahidlo, Bw1hi, Bw1lo, nullptr, H_DIM, H_DIM, H_DIM,
        b1, td, w1, nullptr, Phi, Plo);

    // preds = mask(pre @ w2^T + b2) -> d_out
    wgemm<2><<<dim3(1, PRE_ROWS / 128), 256, GEMM_SMEM>>>(
        Phi, Plo, Bw2hi, Bw2lo, out, K10D, K10D, K10D,
        b2, nullptr, nullptr, lens, nullptr, nullptr);

    // dist_params + lengths (final h is hT buf0 after 256 steps)
    tail_kernel<<<B_DIM, 96>>>(hThi, hTlo, wp, bp, lens, out);
}

// round 16
// speedup vs baseline: 1.3369x; 1.3369x over previous
#include <cuda_runtime.h>
#include <cuda_bf16.h>
#include <mma.h>
#include <math.h>
#include <stdint.h>

using namespace nvcuda;

// ---------------- problem constants ----------------
#define T_DIM 256
#define B_DIM 256
#define D_DIM 128
#define H_DIM 512
#define G3H   1536            // 3*H
#define TM1   255             // T-1
#define K10D  1280            // 10*D
#define PRE_ROWS (B_DIM*TM1)  // 65280
#define PRED_ELEMS (PRE_ROWS*D_DIM)  // 8355840
#define KXP   160             // padded K for x / w_ih (129 -> 160)
#define BH    (B_DIM*H_DIM)   // 131072

// WMMA GEMM geometry
#define BK     32
#define LDSO   48             // operand smem pitch (bf16 elements, 96B)
#define EPAD   132            // epilogue smem pitch (floats)
#define GEMM_SMEM (128*EPAD*4)   // 67584 B -> 2 CTAs/SM fit in 228KB

// persistent GRU geometry (WMMA version)
#define NCTA   128            // 32 unit-chunks x 4 batch-groups
#define GTPB   256            // 8 warps; warps 0-5 do MMA
#define WPITCH 520            // w smem pitch (bf16)
#define WELEMS (48*WPITCH)    // 24960 per array
#define BPITCH 72             // h smem pitch (bf16)
#define STG_EL (2*64*BPITCH)  // 9216 elems per stage (hi+lo)
#define ESM_OFF (2*WELEMS*2 + 2*STG_EL*2)   // 136704 bytes
#define SHOLD_OFF (ESM_OFF + 48*BPITCH*4)   // 150528
#define SOUT_OFF  (SHOLD_OFF + 64*17*4)     // 154880
#define GRU_SMEM  (SOUT_OFF + 4*64*16*2)    // 163072 bytes

// ---------------- scratch (static device arrays) ----------------
__device__ float g_xwT[(size_t)T_DIM * G3H * B_DIM];      // [t][col][b] fp32
__device__ float g_td[PRE_ROWS];
__device__ unsigned g_bar[1028];                          // (T+1) x 4 group counters

// h state: bf16 hi/lo pairs, [buf][b][k] layout
__device__ __nv_bfloat16 g_hThi[2 * BH];
__device__ __nv_bfloat16 g_hTlo[2 * BH];

// bf16 split operands
__device__ __nv_bfloat16 g_Axhi[(size_t)T_DIM * B_DIM * KXP];
__device__ __nv_bfloat16 g_Axlo[(size_t)T_DIM * B_DIM * KXP];
__device__ __nv_bfloat16 g_Bwihhi[(size_t)G3H * KXP];
__device__ __nv_bfloat16 g_Bwihlo[(size_t)G3H * KXP];
__device__ __nv_bfloat16 g_Ahidhi[(size_t)PRE_ROWS * H_DIM];
__device__ __nv_bfloat16 g_Ahidlo[(size_t)PRE_ROWS * H_DIM];
__device__ __nv_bfloat16 g_Bw1hi[(size_t)K10D * H_DIM];
__device__ __nv_bfloat16 g_Bw1lo[(size_t)K10D * H_DIM];
__device__ __nv_bfloat16 g_Bw2hi[(size_t)D_DIM * K10D];
__device__ __nv_bfloat16 g_Bw2lo[(size_t)D_DIM * K10D];
__device__ __nv_bfloat16 g_Phi[(size_t)PRE_ROWS * K10D];
__device__ __nv_bfloat16 g_Plo[(size_t)PRE_ROWS * K10D];

// ---------------- helpers ----------------
__device__ __forceinline__ float fsigmoid(float x) {
    return __fdividef(1.f, 1.f + __expf(-x));
}
__device__ __forceinline__ float ftanh(float x) {
    return 1.f - __fdividef(2.f, __expf(2.f * x) + 1.f);
}

// =======================================================================
// WMMA split-bf16 GEMM: C[M,N] = A[M,K] * B[N,K]^T  (fp32 accumulate)
// acc += Ahi*Bhi + Alo*Bhi + Ahi*Blo
// CTA tile 128x128, 8 warps (4M x 2N), warp tile 32x64, BK=32. 2 CTA/SM.
// MODE 0: xw    -> C[t][col][b] transposed store, + bias
// MODE 1: pre   -> sigmoid(c + td[row]*w1[col*513+512] + bias) -> Phi/Plo
// MODE 2: preds -> c = (t < len[b]-1) ? c+bias : 0  -> C row-major
// =======================================================================
template <int MODE>
__global__ __launch_bounds__(256, 2)
void wgemm(const __nv_bfloat16* __restrict__ Ahi, const __nv_bfloat16* __restrict__ Alo,
           const __nv_bfloat16* __restrict__ Bhi, const __nv_bfloat16* __restrict__ Blo,
           float* __restrict__ C, int K, int lda, int ldb,
           const float* __restrict__ bias, const float* __restrict__ tdv,
           const float* __restrict__ w1f, const int* __restrict__ lengths,
           __nv_bfloat16* __restrict__ Phi, __nv_bfloat16* __restrict__ Plo)
{
    extern __shared__ __align__(16) char smem[];
    __nv_bfloat16* sAhi = (__nv_bfloat16*)smem;            // [128][48]
    __nv_bfloat16* sAlo = sAhi + 128 * LDSO;
    __nv_bfloat16* sBhi = sAlo + 128 * LDSO;
    __nv_bfloat16* sBlo = sBhi + 128 * LDSO;
    float* esm = (float*)smem;                             // [128][132] epilogue

    const int tid = threadIdx.x;
    const int wid = tid >> 5;
    const int lane = tid & 31;
    const int row0 = blockIdx.y * 128;
    const int col0 = blockIdx.x * 128;
    const int wm = (wid & 3) * 32;
    const int wn = (wid >> 2) * 64;

    wmma::fragment<wmma::accumulator, 16, 16, 16, float> acc[2][4];
#pragma unroll
    for (int i = 0; i < 2; i++)
#pragma unroll
        for (int j = 0; j < 4; j++) wmma::fill_fragment(acc[i][j], 0.f);

    // 256 threads cover 128 rows x 32 k in two row halves per operand
    const int lr = tid >> 2, lq = tid & 3;
    const __nv_bfloat16* gAhi0 = Ahi + (size_t)(row0 + lr) * lda + lq * 8;
    const __nv_bfloat16* gAhi1 = gAhi0 + (size_t)64 * lda;
    const __nv_bfloat16* gAlo0 = Alo + (size_t)(row0 + lr) * lda + lq * 8;
    const __nv_bfloat16* gAlo1 = gAlo0 + (size_t)64 * lda;
    const __nv_bfloat16* gBhi0 = Bhi + (size_t)(col0 + lr) * ldb + lq * 8;
    const __nv_bfloat16* gBhi1 = gBhi0 + (size_t)64 * ldb;
    const __nv_bfloat16* gBlo0 = Blo + (size_t)(col0 + lr) * ldb + lq * 8;
    const __nv_bfloat16* gBlo1 = gBlo0 + (size_t)64 * ldb;
    const int soff0 = lr * LDSO + lq * 8;
    const int soff1 = (lr + 64) * LDSO + lq * 8;

#pragma unroll 1
    for (int kc = 0; kc < K; kc += BK) {
        __syncthreads();
        *(uint4*)(sAhi + soff0) = *(const uint4*)(gAhi0 + kc);
        *(uint4*)(sAhi + soff1) = *(const uint4*)(gAhi1 + kc);
        *(uint4*)(sAlo + soff0) = *(const uint4*)(gAlo0 + kc);
        *(uint4*)(sAlo + soff1) = *(const uint4*)(gAlo1 + kc);
        *(uint4*)(sBhi + soff0) = *(const uint4*)(gBhi0 + kc);
        *(uint4*)(sBhi + soff1) = *(const uint4*)(gBhi1 + kc);
        *(uint4*)(sBlo + soff0) = *(const uint4*)(gBlo0 + kc);
        *(uint4*)(sBlo + soff1) = *(const uint4*)(gBlo1 + kc);
        __syncthreads();

#pragma unroll
        for (int ks = 0; ks < BK; ks += 16) {
            wmma::fragment<wmma::matrix_a, 16, 16, 16, __nv_bfloat16, wmma::row_major> ahi[2], alo[2];
#pragma unroll
            for (int i = 0; i < 2; i++) {
                wmma::load_matrix_sync(ahi[i], sAhi + (wm + 16 * i) * LDSO + ks, LDSO);
                wmma::load_matrix_sync(alo[i], sAlo + (wm + 16 * i) * LDSO + ks, LDSO);
            }
#pragma unroll
            for (int j = 0; j < 4; j++) {
                wmma::fragment<wmma::matrix_b, 16, 16, 16, __nv_bfloat16, wmma::col_major> bhi, blo;
                wmma::load_matrix_sync(bhi, sBhi + (wn + 16 * j) * LDSO + ks, LDSO);
                wmma::load_matrix_sync(blo, sBlo + (wn + 16 * j) * LDSO + ks, LDSO);
#pragma unroll
                for (int i = 0; i < 2; i++) {
                    wmma::mma_sync(acc[i][j], ahi[i], bhi, acc[i][j]);
                    wmma::mma_sync(acc[i][j], alo[i], bhi, acc[i][j]);
                    wmma::mma_sync(acc[i][j], ahi[i], blo, acc[i][j]);
                }
            }
        }
    }

    __syncthreads();
#pragma unroll
    for (int i = 0; i < 2; i++)
#pragma unroll
        for (int j = 0; j < 4; j++)
            wmma::store_matrix_sync(esm + (wm + 16 * i) * EPAD + wn + 16 * j,
                                    acc[i][j], EPAD, wmma::mem_row_major);
    __syncthreads();

    if (MODE == 0) {
        const int tt = row0 >> 8;
        const int bb0 = row0 & 255;
#pragma unroll 1
        for (int cc = wid; cc < 128; cc += 8) {
            const int col = col0 + cc;
            const float bz = bias[col];
            float* dst = C + ((size_t)tt * G3H + col) * B_DIM + bb0;
#pragma unroll
            for (int rr = lane; rr < 128; rr += 32)
                dst[rr] = esm[rr * EPAD + cc] + bz;
        }
    } else if (MODE == 1) {
        const int r = tid >> 1, h = tid & 1;
        const int grow = row0 + r;
        const float tdval = tdv[grow];
        const float* esrow = esm + r * EPAD + h * 64;
        const size_t obase = (size_t)grow * K10D + col0 + h * 64;
#pragma unroll
        for (int g = 0; g < 2; g++) {
            uint32_t hp[16], lp[16];
#pragma unroll
            for (int q = 0; q < 16; q++) {
                const int c0 = g * 32 + q * 2;
                const int col = col0 + h * 64 + c0;
                float v0 = esrow[c0]     + bias[col]
                         + tdval * w1f[(size_t)col * 513 + 512];
                float v1 = esrow[c0 + 1] + bias[col + 1]
                         + tdval * w1f[(size_t)(col + 1) * 513 + 512];
                float s0 = fsigmoid(v0);
                float s1 = fsigmoid(v1);
                __nv_bfloat16 h0 = __float2bfloat16(s0);
                __nv_bfloat16 h1 = __float2bfloat16(s1);
                __nv_bfloat16 l0 = __float2bfloat16(s0 - __bfloat162float(h0));
                __nv_bfloat16 l1 = __float2bfloat16(s1 - __bfloat162float(h1));
                __nv_bfloat162 hh = __halves2bfloat162(h0, h1);
                __nv_bfloat162 ll = __halves2bfloat162(l0, l1);
                hp[q] = *(uint32_t*)&hh;
                lp[q] = *(uint32_t*)&ll;
            }
#pragma unroll
            for (int q = 0; q < 4; q++) {
                *(uint4*)(Phi + obase + g * 32 + q * 8) = ((uint4*)hp)[q];
                *(uint4*)(Plo + obase + g * 32 + q * 8) = ((uint4*)lp)[q];
            }
        }
    } else { // MODE 2
        const int r = tid >> 1, h = tid & 1;
        const int grow = row0 + r;
        const int b_ = grow / 255;
        const int t_ = grow - b_ * 255;
        const bool valid = t_ < lengths[b_] - 1;
        const float* esrow = esm + r * EPAD + h * 64;
        float* dst = C + (size_t)grow * D_DIM + col0 + h * 64;
#pragma unroll
        for (int q = 0; q < 16; q++) {
            const int c0 = q * 4;
            const int col = col0 + h * 64 + c0;
            float4 v;
            v.x = valid ? (esrow[c0]     + bias[col])     : 0.f;
            v.y = valid ? (esrow[c0 + 1] + bias[col + 1]) : 0.f;
            v.z = valid ? (esrow[c0 + 2] + bias[col + 2]) : 0.f;
            v.w = valid ? (esrow[c0 + 3] + bias[col + 3]) : 0.f;
            *(float4*)(dst + c0) = v;
        }
    }
}

// =======================================================================
// conversions: fp32 -> bf16 hi/lo with zero-padding
// =======================================================================
__global__ void conv_pad(const float* __restrict__ src,
                         __nv_bfloat16* __restrict__ hi,
                         __nv_bfloat16* __restrict__ lo,
                         int rows, int sld, int dld, int valid)
{
    int i = blockIdx.x * 256 + threadIdx.x;
    if (i >= rows * dld) return;
    int r = i / dld, c = i - r * dld;
    float v = (c < valid) ? src[(size_t)r * sld + c] : 0.f;
    __nv_bfloat16 h = __float2bfloat16(v);
    hi[i] = h;
    lo[i] = __float2bfloat16(v - __bfloat162float(h));
}

// =======================================================================
// Persistent GRU on tensor cores. 128 CTAs (1/SM), 256 steps, 8 warps.
// CTA (jc,bgi): units [jc*16,+16) x 3 gates, batches [bgi*64,+64).
// Per-batch-group (32 CTA) barriers. hold captured from staged SMEM.
// Epilogue outputs staged in SMEM then written as 32B rows.
// =======================================================================
__global__ __launch_bounds__(GTPB, 1)
void gru_wmma(const float* __restrict__ h0,
              const float* __restrict__ xwT,
              const float* __restrict__ w_hh,
              const float* __restrict__ b_hh,
              const int*   __restrict__ lengths,
              __nv_bfloat16* __restrict__ hThi,
              __nv_bfloat16* __restrict__ hTlo,
              __nv_bfloat16* __restrict__ Ahidhi,
              __nv_bfloat16* __restrict__ Ahidlo,
              unsigned* __restrict__ bar)
{
    extern __shared__ __align__(16) char sm[];
    __nv_bfloat16* sWhi = (__nv_bfloat16*)sm;             // [48][520]
    __nv_bfloat16* sWlo = sWhi + WELEMS;
    __nv_bfloat16* sB   = sWlo + WELEMS;                  // [2 stg][2][64][72]
    float* esm = (float*)(sm + ESM_OFF);                  // [48][72]
    float* sHold = (float*)(sm + SHOLD_OFF);              // [64][17]
    __nv_bfloat16* sOhi = (__nv_bfloat16*)(sm + SOUT_OFF);        // [64][16]
    __nv_bfloat16* sOlo = sOhi + 64 * 16;
    __nv_bfloat16* sAh  = sOlo + 64 * 16;
    __nv_bfloat16* sAl  = sAh  + 64 * 16;

    const int tid = threadIdx.x;
    const int wid = tid >> 5;
    const int jc  = blockIdx.x & 31;
    const int bgi = blockIdx.x >> 5;
    const int ubase = jc * 16;
    const int bbase = bgi * 64;
    const int cu = jc >> 2;             // chunk holding this CTA's own units
    const int koff = ubase & 63;

    // ---- one-time: w_hh slice -> SMEM bf16 hi/lo, rows = g*16+u
    for (int i = tid; i < 48 * 512; i += GTPB) {
        int row = i >> 9, k = i & 511;
        int g = row >> 4, u = row & 15;
        float v = w_hh[(size_t)(g * H_DIM + ubase + u) * H_DIM + k];
        __nv_bfloat16 h = __float2bfloat16(v);
        sWhi[row * WPITCH + k] = h;
        sWlo[row * WPITCH + k] = __float2bfloat16(v - __bfloat162float(h));
    }
    // ---- one-time: own tile of h0 -> hT buf0 ([b][k] bf16 pair)
    for (int i = tid; i < 1024; i += GTPB) {
        int b = i >> 4, u = i & 15;
        float v = h0[(size_t)(bbase + b) * H_DIM + ubase + u];
        __nv_bfloat16 h = __float2bfloat16(v);
        size_t a = (size_t)(bbase + b) * H_DIM + ubase + u;
        hThi[a] = h;
        hTlo[a] = __float2bfloat16(v - __bfloat162float(h));
    }
    __syncthreads();
    if (tid == 0) {
        __threadfence();
        atomicAdd(&bar[bgi], 1u);
        volatile unsigned* f = &bar[bgi];
        while (*f < 32u) __nanosleep(32);
    }
    __syncthreads();

    const int g_w = wid >> 1;      // compute-warp gate (wid<6)
    const int bh_w = wid & 1;      // compute-warp batch half

    for (int t = 0; t < T_DIM; t++) {
        const __nv_bfloat16* hHi = hThi + (size_t)(t & 1) * BH;
        const __nv_bfloat16* hLo = hTlo + (size_t)(t & 1) * BH;
        __nv_bfloat16* nHi = hThi + (size_t)((t + 1) & 1) * BH;
        __nv_bfloat16* nLo = hTlo + (size_t)((t + 1) & 1) * BH;

        wmma::fragment<wmma::accumulator, 16, 16, 16, float> acc[2];
        wmma::fill_fragment(acc[0], 0.f);
        wmma::fill_fragment(acc[1], 0.f);

        // prefetch chunk 0: 1024 uint4 (hi:512, lo:512) / 256 threads = 4
        uint4 pf[4];
#pragma unroll
        for (int s = 0; s < 4; s++) {
            int j = tid + s * GTPB;
            int arr = j >> 9, jj = j & 511;
            int b = jj >> 3, q = jj & 7;
            const __nv_bfloat16* src = arr ? hLo : hHi;
            pf[s] = __ldcg((const uint4*)(src + (size_t)(bbase + b) * H_DIM + q * 8));
        }

#pragma unroll 1
        for (int c = 0; c < 8; c++) {
#pragma unroll
            for (int s = 0; s < 4; s++) {
                int j = tid + s * GTPB;
                int arr = j >> 9, jj = j & 511;
                int b = jj >> 3, q = jj & 7;
                *(uint4*)(sB + (c & 1) * STG_EL + arr * (64 * BPITCH)
                          + b * BPITCH + q * 8) = pf[s];
            }
            if (c < 7) {
#pragma unroll
                for (int s = 0; s < 4; s++) {
                    int j = tid + s * GTPB;
                    int arr = j >> 9, jj = j & 511;
                    int b = jj >> 3, q = jj & 7;
                    const __nv_bfloat16* src = arr ? hLo : hHi;
                    pf[s] = __ldcg((const uint4*)(src + (size_t)(bbase + b) * H_DIM
                                                  + (c + 1) * 64 + q * 8));
                }
            }
            __syncthreads();

            // capture hold (this CTA's own unit slice) from the staged chunk
            if (c == cu) {
                const __nv_bfloat16* shi = sB + (c & 1) * STG_EL;
                const __nv_bfloat16* slo = shi + 64 * BPITCH;
#pragma unroll
                for (int s = 0; s < 4; s++) {
                    int i = tid + s * GTPB;
                    int b = i & 63, u = i >> 6;
                    sHold[b * 17 + u] =
                        __bfloat162float(shi[b * BPITCH + koff + u]) +
                        __bfloat162float(slo[b * BPITCH + koff + u]);
                }
            }

            if (wid < 6) {
                const __nv_bfloat16* sHhi = sB + (c & 1) * STG_EL;
                const __nv_bfloat16* sHlo = sHhi + 64 * BPITCH;
#pragma unroll
                for (int ks = 0; ks < 64; ks += 16) {
                    wmma::fragment<wmma::matrix_a, 16, 16, 16, __nv_bfloat16, wmma::row_major> ahi, alo;
                    wmma::load_matrix_sync(ahi, sWhi + (g_w * 16) * WPITCH + c * 64 + ks, WPITCH);
                    wmma::load_matrix_sync(alo, sWlo + (g_w * 16) * WPITCH + c * 64 + ks, WPITCH);
#pragma unroll
                    for (int j = 0; j < 2; j++) {
                        wmma::fragment<wmma::matrix_b, 16, 16, 16, __nv_bfloat16, wmma::col_major> bhi, blo;
                        const int ncol = bh_w * 32 + j * 16;
                        wmma::load_matrix_sync(bhi, sHhi + ncol * BPITCH + ks, BPITCH);
                        wmma::load_matrix_sync(blo, sHlo + ncol * BPITCH + ks, BPITCH);
                        wmma::mma_sync(acc[j], ahi, bhi, acc[j]);
                        wmma::mma_sync(acc[j], alo, bhi, acc[j]);
                        wmma::mma_sync(acc[j], ahi, blo, acc[j]);
                    }
                }
            }
        }

        // stage gate pre-activations to esm [48][72]
        if (wid < 6) {
#pragma unroll
            for (int j = 0; j < 2; j++)
                wmma::store_matrix_sync(esm + (g_w * 16) * BPITCH + bh_w * 32 + j * 16,
                                        acc[j], BPITCH, wmma::mem_row_major);
        }
        __syncthreads();

        // ---- epilogue: 1024 outputs (16 units x 64 batches), staged to SMEM
#pragma unroll
        for (int s = 0; s < 4; s++) {
            int i = tid + s * GTPB;
            int u = i >> 6, b = i & 63;
            int ug = ubase + u, bg = bbase + b;
            float ar = esm[(0 * 16 + u) * BPITCH + b];
            float az = esm[(1 * 16 + u) * BPITCH + b];
            float an = esm[(2 * 16 + u) * BPITCH + b];
            size_t xb = ((size_t)t * G3H + ug) * B_DIM + bg;
            float xr = __ldg(xwT + xb);
            float xz = __ldg(xwT + xb + (size_t)H_DIM * B_DIM);
            float xn = __ldg(xwT + xb + (size_t)2 * H_DIM * B_DIM);
            float hold = sHold[b * 17 + u];
            float r = fsigmoid(xr + ar + b_hh[ug]);
            float z = fsigmoid(xz + az + b_hh[H_DIM + ug]);
            float n = ftanh(xn + r * (an + b_hh[2 * H_DIM + ug]));
            float hnew = (1.f - z) * n + z * hold;
            bool valid = t < lengths[bg];
            float hout = valid ? hnew : hold;
            __nv_bfloat16 hh = __float2bfloat16(hout);
            sOhi[b * 16 + u] = hh;
            sOlo[b * 16 + u] = __float2bfloat16(hout - __bfloat162float(hh));
            float hv = valid ? hnew : 0.f;
            __nv_bfloat16 ah = __float2bfloat16(hv);
            sAh[b * 16 + u] = ah;
            sAl[b * 16 + u] = __float2bfloat16(hv - __bfloat162float(ah));
        }
        __syncthreads();

        // ---- store phase: 32B rows, one array per 64-thread group
        {
            const int g2 = tid >> 6, b = tid & 63;
            const __nv_bfloat16* srow;
            __nv_bfloat16* dst = nullptr;
            if (g2 == 0) {
                srow = sOhi + b * 16;
                dst = nHi + (size_t)(bbase + b) * H_DIM + ubase;
            } else if (g2 == 1) {
                srow = sOlo + b * 16;
                dst = nLo + (size_t)(bbase + b) * H_DIM + ubase;
            } else if (g2 == 2) {
                srow = sAh + b * 16;
                if (t < TM1)
                    dst = Ahidhi + ((size_t)(bbase + b) * TM1 + t) * H_DIM + ubase;
            } else {
                srow = sAl + b * 16;
                if (t < TM1)
                    dst = Ahidlo + ((size_t)(bbase + b) * TM1 + t) * H_DIM + ubase;
            }
            if (dst) {
                uint4 v0 = *(const uint4*)(srow);
                uint4 v1 = *(const uint4*)(srow + 8);
                *(uint4*)(dst) = v0;
                *(uint4*)(dst + 8) = v1;
            }
        }

        __syncthreads();
        if (t < T_DIM - 1) {
            if (tid == 0) {
                __threadfence();
                unsigned idx = (unsigned)(t + 1) * 4u + (unsigned)bgi;
                atomicAdd(&bar[idx], 1u);
                volatile unsigned* f = &bar[idx];
                while (*f < 32u) __nanosleep(32);
            }
            __syncthreads();
        }
    }
}

// =======================================================================
__global__ void td_kernel(const float* __restrict__ x, float* __restrict__ td)
{
    int i = blockIdx.x * 256 + threadIdx.x;
    if (i < PRE_ROWS) {
        int b = i / 255;
        int t = i - b * 255;
        td[i] = x[(size_t)((t + 1) * B_DIM + b) * (D_DIM + 1)]
              - x[(size_t)(t * B_DIM + b) * (D_DIM + 1)];
    }
}

// =======================================================================
// dist_params + lengths; final h is hT buf0, [b][k] bf16 pair layout
// =======================================================================
__global__ void tail_kernel(const __nv_bfloat16* __restrict__ hHi,
                            const __nv_bfloat16* __restrict__ hLo,
                            const float* __restrict__ wp,
                            const float* __restrict__ bp,
                            const int* __restrict__ lengths,
                            float* __restrict__ out)
{
    int b = blockIdx.x;
    int w = threadIdx.x >> 5;
    int lane = threadIdx.x & 31;
    float s = 0.f;
    for (int k = lane; k < H_DIM; k += 32) {
        float hv = __bfloat162float(hHi[(size_t)b * H_DIM + k])
                 + __bfloat162float(hLo[(size_t)b * H_DIM + k]);
        s += hv * wp[(size_t)w * H_DIM + k];
    }
#pragma unroll
    for (int o = 16; o; o >>= 1) s += __shfl_xor_sync(0xffffffffu, s, o);
    if (lane == 0)
        out[PRED_ELEMS + b * 3 + w] = expf(-(s + bp[w]));
    if (threadIdx.x == 0)
        out[PRED_ELEMS + B_DIM * 3 + b] = (float)lengths[b];
}

// =======================================================================
extern "C" void kernel_launch(void* const* d_in, const int* in_sizes, int n_in,
                              void* d_out, int out_size)
{
    const float* x    = (const float*)d_in[0];
    const float* h0   = (const float*)d_in[1];
    const int*   lens = (const int*)  d_in[2];
    const float* w_ih = (const float*)d_in[3];
    const float* w_hh = (const float*)d_in[4];
    const float* b_ih = (const float*)d_in[5];
    const float* b_hh = (const float*)d_in[6];
    const float* w1   = (const float*)d_in[7];
    const float* b1   = (const float*)d_in[8];
    const float* w2   = (const float*)d_in[9];
    const float* b2   = (const float*)d_in[10];
    const float* wp   = (const float*)d_in[11];
    const float* bp   = (const float*)d_in[12];
    float* out = (float*)d_out;

    float *xwT, *td;
    unsigned* bar;
    __nv_bfloat16 *hThi, *hTlo;
    __nv_bfloat16 *Axhi, *Axlo, *Bwihhi, *Bwihlo, *Ahidhi, *Ahidlo;
    __nv_bfloat16 *Bw1hi, *Bw1lo, *Bw2hi, *Bw2lo, *Phi, *Plo;
    cudaGetSymbolAddress((void**)&xwT,    g_xwT);
    cudaGetSymbolAddress((void**)&td,     g_td);
    cudaGetSymbolAddress((void**)&bar,    g_bar);
    cudaGetSymbolAddress((void**)&hThi,   g_hThi);
    cudaGetSymbolAddress((void**)&hTlo,   g_hTlo);
    cudaGetSymbolAddress((void**)&Axhi,   g_Axhi);
    cudaGetSymbolAddress((void**)&Axlo,   g_Axlo);
    cudaGetSymbolAddress((void**)&Bwihhi, g_Bwihhi);
    cudaGetSymbolAddress((void**)&Bwihlo, g_Bwihlo);
    cudaGetSymbolAddress((void**)&Ahidhi, g_Ahidhi);
    cudaGetSymbolAddress((void**)&Ahidlo, g_Ahidlo);
    cudaGetSymbolAddress((void**)&Bw1hi,  g_Bw1hi);
    cudaGetSymbolAddress((void**)&Bw1lo,  g_Bw1lo);
    cudaGetSymbolAddress((void**)&Bw2hi,  g_Bw2hi);
    cudaGetSymbolAddress((void**)&Bw2lo,  g_Bw2lo);
    cudaGetSymbolAddress((void**)&Phi,    g_Phi);
    cudaGetSymbolAddress((void**)&Plo,    g_Plo);

    cudaFuncSetAttribute(gru_wmma,
                         cudaFuncAttributeMaxDynamicSharedMemorySize, GRU_SMEM);
    cudaFuncSetAttribute(wgemm<0>,
                         cudaFuncAttributeMaxDynamicSharedMemorySize, GEMM_SMEM);
    cudaFuncSetAttribute(wgemm<1>,
                         cudaFuncAttributeMaxDynamicSharedMemorySize, GEMM_SMEM);
    cudaFuncSetAttribute(wgemm<2>,
                         cudaFuncAttributeMaxDynamicSharedMemorySize, GEMM_SMEM);

    cudaMemsetAsync(bar, 0, 1028 * sizeof(unsigned));

    td_kernel<<<255, 256>>>(x, td);

    // conversions for gemm0 operands
    conv_pad<<<(T_DIM * B_DIM * KXP + 255) / 256, 256>>>(
        x, Axhi, Axlo, T_DIM * B_DIM, D_DIM + 1, KXP, D_DIM + 1);
    conv_pad<<<(G3H * KXP + 255) / 256, 256>>>(
        w_ih, Bwihhi, Bwihlo, G3H, D_DIM + 1, KXP, D_DIM + 1);
    // weights for later gemms
    conv_pad<<<(K10D * H_DIM + 255) / 256, 256>>>(
        w1, Bw1hi, Bw1lo, K10D, H_DIM + 1, H_DIM, H_DIM);
    conv_pad<<<(D_DIM * K10D + 255) / 256, 256>>>(
        w2, Bw2hi, Bw2lo, D_DIM, K10D, K10D, K10D);

    // xwT = (x @ w_ih^T + b_ih) transposed -> [t][col][b]
    wgemm<0><<<dim3(G3H / 128, (T_DIM * B_DIM) / 128), 256, GEMM_SMEM>>>(
        Axhi, Axlo, Bwihhi, Bwihlo, xwT, KXP, KXP, KXP,
        b_ih, nullptr, nullptr, nullptr, nullptr, nullptr);

    // persistent tensor-core GRU (all 256 steps); writes Ahid directly
    gru_wmma<<<NCTA, GTPB, GRU_SMEM>>>(h0, xwT, w_hh, b_hh, lens,
                                       hThi, hTlo, Ahidhi, Ahidlo, bar);

    // pre = sigmoid(hwt[:, :-1] @ w1^T + b1) -> Phi/Plo (bf16 split)
    wgemm<1><<<dim3(K10D / 128, PRE_ROWS / 128), 256, GEMM_SMEM>>>(
        Ahidhi, Ahidlo, Bw1hi, Bw1lo, nullptr, H_DIM, H_DIM, H_DIM,
        b1, td, w1, nullptr, Phi, Plo);

    // preds = mask(pre @ w2^T + b2) -> d_out
    wgemm<2><<<dim3(1, PRE_ROWS / 128), 256, GEMM_SMEM>>>(
        Phi, Plo, Bw2hi, Bw2lo, out, K10D, K10D, K10D,
        b2, nullptr, nullptr, lens, nullptr, nullptr);

    // dist_params + lengths (final h is hT buf0 after 256 steps)
    tail_kernel<<<B_DIM, 96>>>(hThi, hTlo, wp, bp, lens, out);
}